// round 11
// baseline (speedup 1.0000x reference)
#include <cuda_runtime.h>
#include <cuda_fp16.h>
#include <math.h>

// ---------------------------------------------------------------------------
// VariationalLinear fused kernel, round 11 (sm_100a)
//   out(256,4096) = x @ W^T + b,  W = mu + softplus(rho)*eps_w, + analytic KL
//   (prior_mu=0, prior_sigma=0.1 folded as constants; validated R8)
//
// R11 vs R9 (85.9us, cp.async ISSUE-RATE bound: ~1536 LSU ops/chunk/CTA
// @ ~1 op/cy/SM == measured dur; L1 50%):
//  - weight staging -> cp.async.bulk 64B/row (192 ops/chunk, was 768+256dup),
//    completion via mbarrier expect_tx parity (4 raw stages)
//  - X keeps cp.async16 in its own wait_group domain, XSTG=3
//  - dup-stream bug removed; skeleton otherwise identical (KC=16, Wg double,
//    one __syncthreads/chunk, ldmatrix, fp16 m16n8k16 / fp32 acc, 512 thr)
// ---------------------------------------------------------------------------

#define BATCH   256
#define IN_F    4096
#define OUT_F   4096
#define NT      64
#define KSPLIT  4
#define KSEG    (IN_F / KSPLIT)    // 1024
#define KC      16
#define NCHUNK  (KSEG / KC)        // 64
#define XSTG    3
#define RSTG    4
#define XSH     24                 // X row stride (halves): 16 data + 8 pad
#define WSH     24                 // Wg row stride (halves)
#define THREADS 512

#define XS_BYTES   (BATCH * XSH * 2)    // 12288
#define RAW_FL     (3 * NT * KC)        // 3072 floats (mu, rho, epsw)
#define RAW_BYTES  (RAW_FL * 4)         // 12288 (per stage; 4096 per stream)
#define WG_BYTES   (NT * WSH * 2)       // 3072
#define SMEM_BYTES (XSTG * XS_BYTES + RSTG * RAW_BYTES + 2 * WG_BYTES) // 92160

#define KL_C0  (-2.80258509299f)        // log(0.1) - 0.5

__device__ __align__(16) __half g_x_h[BATCH * IN_F];   // x in fp16, row-major

__device__ __forceinline__ void cp_async16(void* smem_dst, const void* gsrc) {
    unsigned saddr = (unsigned)__cvta_generic_to_shared(smem_dst);
    asm volatile("cp.async.cg.shared.global [%0], [%1], 16;"
                 :: "r"(saddr), "l"(gsrc));
}

__device__ __forceinline__ void cp_bulk(unsigned smem_dst, const void* gsrc,
                                        unsigned bytes, unsigned mbar) {
    asm volatile(
        "cp.async.bulk.shared::cluster.global.mbarrier::complete_tx::bytes "
        "[%0], [%1], %2, [%3];"
        :: "r"(smem_dst), "l"(gsrc), "r"(bytes), "r"(mbar) : "memory");
}

__device__ __forceinline__ void mbar_init(unsigned mbar, unsigned cnt) {
    asm volatile("mbarrier.init.shared.b64 [%0], %1;" :: "r"(mbar), "r"(cnt)
                 : "memory");
}

__device__ __forceinline__ void mbar_expect_tx(unsigned mbar, unsigned bytes) {
    asm volatile("mbarrier.arrive.expect_tx.shared.b64 _, [%0], %1;"
                 :: "r"(mbar), "r"(bytes) : "memory");
}

__device__ __forceinline__ void mbar_wait(unsigned mbar, unsigned parity) {
    asm volatile(
        "{\n\t"
        ".reg .pred P;\n\t"
        "WAIT_%=:\n\t"
        "mbarrier.try_wait.parity.acquire.cta.shared::cta.b64 P, [%0], %1, 0x989680;\n\t"
        "@P bra.uni DONE_%=;\n\t"
        "bra.uni WAIT_%=;\n\t"
        "DONE_%=:\n\t"
        "}"
        :: "r"(mbar), "r"(parity) : "memory");
}

__device__ __forceinline__ void ldsm_x4(unsigned& r0, unsigned& r1,
                                        unsigned& r2, unsigned& r3,
                                        unsigned saddr) {
    asm volatile("ldmatrix.sync.aligned.m8n8.x4.shared.b16 {%0,%1,%2,%3}, [%4];"
                 : "=r"(r0), "=r"(r1), "=r"(r2), "=r"(r3) : "r"(saddr));
}

__device__ __forceinline__ void mma_f16(float* c, const unsigned* a,
                                        unsigned b0, unsigned b1) {
    asm volatile(
        "mma.sync.aligned.m16n8k16.row.col.f32.f16.f16.f32 "
        "{%0,%1,%2,%3}, {%4,%5,%6,%7}, {%8,%9}, {%0,%1,%2,%3};"
        : "+f"(c[0]), "+f"(c[1]), "+f"(c[2]), "+f"(c[3])
        : "r"(a[0]), "r"(a[1]), "r"(a[2]), "r"(a[3]), "r"(b0), "r"(b1));
}

__device__ __forceinline__ float softplus_fast(float r) {
    return (r > 15.f) ? r : __logf(1.f + __expf(r));
}

// ---------------------------------------------------------------------------
// Prep: out <- bias broadcast, KL slot <- 0, x -> fp16 scratch.
// ---------------------------------------------------------------------------
__global__ void vl_prep(const float* __restrict__ x,
                        const float* __restrict__ bmu,
                        const float* __restrict__ brho,
                        const float* __restrict__ epsb,
                        float* __restrict__ out, int out_size) {
    int i = blockIdx.x * blockDim.x + threadIdx.x;
    if (i < BATCH * OUT_F) {
        int col = i & (OUT_F - 1);
        out[i] = fmaf(softplus_fast(brho[col]), epsb[col], bmu[col]);
    } else if (i < out_size) {
        out[i] = 0.f;
    }
    if (i < BATCH * IN_F)
        g_x_h[i] = __float2half_rn(x[i]);
}

// ---------------------------------------------------------------------------
// Main fused kernel: 512 threads, warp owns one m16 tile; bulk-DMA weights
// ---------------------------------------------------------------------------
__global__ void __launch_bounds__(THREADS, 2)
vl_main(const float* __restrict__ mu, const float* __restrict__ rho,
        const float* __restrict__ epsw,
        float* __restrict__ out, float* __restrict__ klout) {
    extern __shared__ char smbase[];
    __half* Xs  = (__half*)smbase;                               // [3][256][XSH]
    float*  Raw = (float*)(smbase + XSTG * XS_BYTES);            // [4][3][1024]
    __shared__ __align__(8) unsigned long long rawmbar[RSTG];
    __shared__ float klred[16];

    const unsigned sbase = (unsigned)__cvta_generic_to_shared(smbase);
    const unsigned xs_b  = sbase;
    const unsigned raw_b = sbase + XSTG * XS_BYTES;
    const unsigned wg_b  = sbase + XSTG * XS_BYTES + RSTG * RAW_BYTES;
    const unsigned mb_b  = (unsigned)__cvta_generic_to_shared(rawmbar);

    const int tid  = threadIdx.x;
    const int warp = tid >> 5;                 // 0..15
    const int lane = tid & 31;
    const int g    = lane >> 2;
    const int t    = lane & 3;

    const int ntile = blockIdx.x >> 2;
    const int kseg  = blockIdx.x & 3;
    const int n0    = ntile * NT;
    const int kbase = kseg * KSEG;
    const int m16   = warp * 16;

    float acc[8][4];
#pragma unroll
    for (int nt = 0; nt < 8; nt++)
#pragma unroll
        for (int i = 0; i < 4; i++) acc[nt][i] = 0.f;

    float klsum = 0.f;

    // Wgen: thread owns 2 consecutive elements of the 64x16 tile
    const int we   = tid * 2;                  // 0..1022
    const int wrow = we >> 4;                  // 0..63
    const int wk   = we & 15;

    // bulk staging: tid<192 -> stream s=tid>>6, row=tid&63, 64B per row
    const int  bs   = tid >> 6;                // 0..2 (valid when tid<192)
    const int  brow = tid & 63;
    const long bofs = (long)(n0 + brow) * IN_F + kbase;
    const float* streams[3] = { mu, rho, epsw };
    const float* bsrc = streams[bs & 3 ? bs : bs];   // keep simple; bs in 0..7
    const unsigned bdst_off = bs * 4096 + brow * 64; // bytes within raw stage

    // A ldmatrix offset (bytes): row = m16 + (lane&15), kofs = (lane>>4)*8
    const unsigned a_off =
        ((m16 + (lane & 15)) * XSH + ((lane >> 4) << 3)) * 2;
    // B ldmatrix base offset (pair p=0)
    const unsigned b_off0 =
        ((((lane >> 4) << 3) + (lane & 7)) * WSH + (((lane >> 3) & 1) << 3)) * 2;

    auto xPf = [&](int c) {                    // X chunk c -> stage c%3
        if (c < NCHUNK) {
            const int k0 = kbase + c * KC;
            __half* xd = Xs + (c % XSTG) * (BATCH * XSH);
            int row = tid >> 1;
            int seg = tid & 1;
            cp_async16(xd + row * XSH + seg * 8,
                       g_x_h + (long)row * IN_F + k0 + seg * 8);
        }
        asm volatile("cp.async.commit_group;");
    };
    auto rPf = [&](int c) {                    // weights chunk c -> stage c&3
        if (c < NCHUNK) {
            const unsigned mb = mb_b + (c & 3) * 8;
            if (tid == 0) mbar_expect_tx(mb, RAW_BYTES);
            if (tid < 192)
                cp_bulk(raw_b + (c & 3) * RAW_BYTES + bdst_off,
                        streams[bs] + bofs + c * KC, 64, mb);
        }
    };

    // Wgen(k): raw stage k&3 -> Wg[k&1]; KL with prior constants folded
    auto wgen = [&](int k) {
        mbar_wait(mb_b + (k & 3) * 8, (k >> 2) & 1);
        const float* rb = Raw + (k & 3) * RAW_FL;
        float2 m2 = *reinterpret_cast<const float2*>(rb + 0 * NT * KC + we);
        float2 r2 = *reinterpret_cast<const float2*>(rb + 1 * NT * KC + we);
        float2 e2 = *reinterpret_cast<const float2*>(rb + 2 * NT * KC + we);
        const float mv[2] = {m2.x, m2.y};
        const float rv[2] = {r2.x, r2.y};
        const float ev[2] = {e2.x, e2.y};
        float wv[2];
#pragma unroll
        for (int q = 0; q < 2; q++) {
            float sg = __logf(1.f + __expf(rv[q]));    // softplus
            wv[q] = fmaf(sg, ev[q], mv[q]);
            klsum += fmaf(50.f, fmaf(sg, sg, mv[q] * mv[q]),
                          KL_C0 - __logf(sg));
        }
        __half2 p0 = __floats2half2_rn(wv[0], wv[1]);
        *reinterpret_cast<__half2*>(
            (__half*)(smbase + XSTG * XS_BYTES + RSTG * RAW_BYTES)
            + (k & 1) * (NT * WSH) + wrow * WSH + wk) = p0;
    };

    // ---- prologue ----
    if (tid == 0) {
#pragma unroll
        for (int s = 0; s < RSTG; s++) mbar_init(mb_b + s * 8, 1);
    }
    __syncthreads();                           // mbars visible
    asm volatile("fence.proxy.async.shared::cta;" ::: "memory");
    rPf(0);
    rPf(1);
    rPf(2);
    xPf(0);
    xPf(1);
    wgen(0);                                   // waits mbar[0] parity 0
    __syncthreads();                           // Wg[0] visible before MMA(0)

    for (int c = 0; c < NCHUNK; c++) {
        asm volatile("cp.async.wait_group 1;");  // X(c) landed (X(c+1) inflight)
        __syncthreads();                         // one barrier per chunk

        xPf(c + 2);                              // stage (c+2)%3 (read @ c-1)
        asm volatile("fence.proxy.async.shared::cta;" ::: "memory");
        rPf(c + 3);                              // stage (c-1)&3 (read @ c-2)

        if (c + 1 < NCHUNK) wgen(c + 1);         // waits mbar, -> Wg[(c+1)&1]

        // ---- MMA(c): A (one m16 tile) + B via ldmatrix ----
        const unsigned xa = xs_b + (c % XSTG) * XS_BYTES + a_off;
        unsigned a0[4];
        ldsm_x4(a0[0], a0[1], a0[2], a0[3], xa);

        const unsigned wb = wg_b + (c & 1) * WG_BYTES + b_off0;
#pragma unroll
        for (int p = 0; p < 4; p++) {
            unsigned b0, b1, b2, b3;
            ldsm_x4(b0, b1, b2, b3, wb + p * 16 * WSH * 2);
            mma_f16(acc[2 * p],     a0, b0, b1);
            mma_f16(acc[2 * p + 1], a0, b2, b3);
        }
    }

    // ---- epilogue: atomic-accumulate partial output (bias already in out) ----
    {
        int r0 = m16 + g;
#pragma unroll
        for (int nt = 0; nt < 8; nt++) {
            int col = n0 + nt * 8 + 2 * t;
            atomicAdd(&out[(long)r0 * OUT_F + col],           acc[nt][0]);
            atomicAdd(&out[(long)r0 * OUT_F + col + 1],       acc[nt][1]);
            atomicAdd(&out[(long)(r0 + 8) * OUT_F + col],     acc[nt][2]);
            atomicAdd(&out[(long)(r0 + 8) * OUT_F + col + 1], acc[nt][3]);
        }
    }

    // ---- KL reduction ----
#pragma unroll
    for (int o = 16; o; o >>= 1)
        klsum += __shfl_xor_sync(0xFFFFFFFFu, klsum, o);
    if (lane == 0) klred[warp] = klsum;
    __syncthreads();
    if (tid == 0) {
        float s = 0.f;
#pragma unroll
        for (int i = 0; i < 16; i++) s += klred[i];
        atomicAdd(klout, s);
    }
}

// ---------------------------------------------------------------------------
extern "C" void kernel_launch(void* const* d_in, const int* in_sizes, int n_in,
                              void* d_out, int out_size) {
    const float* x    = (const float*)d_in[0];
    const float* wmu  = (const float*)d_in[1];
    const float* wrho = (const float*)d_in[2];
    const float* bmu  = (const float*)d_in[3];
    const float* brho = (const float*)d_in[4];
    const float* epsw = (const float*)d_in[5];
    const float* epsb = (const float*)d_in[6];
    float* out = (float*)d_out;

    int n = BATCH * IN_F;
    if (out_size > n) n = out_size;
    vl_prep<<<(n + 255) / 256, 256>>>(x, bmu, brho, epsb, out, out_size);

    cudaFuncSetAttribute(vl_main, cudaFuncAttributeMaxDynamicSharedMemorySize,
                         SMEM_BYTES);
    vl_main<<<(OUT_F / NT) * KSPLIT, THREADS, SMEM_BYTES>>>(
        wmu, wrho, epsw, out, out + (out_size - 1));
}

// round 12
// speedup vs baseline: 1.5582x; 1.5582x over previous
#include <cuda_runtime.h>
#include <cuda_fp16.h>
#include <math.h>

// ---------------------------------------------------------------------------
// VariationalLinear fused kernel, round 12 (sm_100a)
//   out(256,4096) = x @ W^T + b,  W = mu + softplus(rho)*eps_w, + analytic KL
//   (prior_mu=0, prior_sigma=0.1 folded as constants; validated R8)
//
// R12 = revert R11 (bulk-DMA regression) to the R10 skeleton, plus:
//  - duplicate stream-2 staging removed (R9/R10 bug: -256 thread-ops/chunk)
//  - MMA(c) issued BEFORE wgen(c+1): tensor burst first, MUFU overlaps it
//  - epilogue red.global.add.v2.f32: 32 -> 16 reduction ops per thread
// Skeleton: 512 thr, warp=m16 tile, KC=16, X 2 stages, raw 4 stages,
// Wg double-buffered, one __syncthreads/chunk, ldmatrix, fp16 MMA/fp32 acc.
// ---------------------------------------------------------------------------

#define BATCH   256
#define IN_F    4096
#define OUT_F   4096
#define NT      64
#define KSPLIT  4
#define KSEG    (IN_F / KSPLIT)    // 1024
#define KC      16
#define NCHUNK  (KSEG / KC)        // 64
#define XSTG    2
#define RSTG    4
#define XSH     24                 // X row stride (halves): 16 data + 8 pad
#define WSH     24                 // Wg row stride (halves)
#define THREADS 512

#define XS_BYTES  (BATCH * XSH * 2)     // 12288
#define RAW_FL    (3 * NT * KC)         // 3072 floats (mu, rho, epsw)
#define RAW_BYTES (RAW_FL * 4)          // 12288
#define WG_BYTES  (NT * WSH * 2)        // 3072
#define SMEM_BYTES (XSTG * XS_BYTES + RSTG * RAW_BYTES + 2 * WG_BYTES) // 79872

#define KL_C0  (-2.80258509299f)        // log(0.1) - 0.5

__device__ __align__(16) __half g_x_h[BATCH * IN_F];   // x in fp16, row-major

__device__ __forceinline__ void cp_async16(void* smem_dst, const void* gsrc) {
    unsigned saddr = (unsigned)__cvta_generic_to_shared(smem_dst);
    asm volatile("cp.async.cg.shared.global [%0], [%1], 16;"
                 :: "r"(saddr), "l"(gsrc));
}

__device__ __forceinline__ void ldsm_x4(unsigned& r0, unsigned& r1,
                                        unsigned& r2, unsigned& r3,
                                        unsigned saddr) {
    asm volatile("ldmatrix.sync.aligned.m8n8.x4.shared.b16 {%0,%1,%2,%3}, [%4];"
                 : "=r"(r0), "=r"(r1), "=r"(r2), "=r"(r3) : "r"(saddr));
}

__device__ __forceinline__ void mma_f16(float* c, const unsigned* a,
                                        unsigned b0, unsigned b1) {
    asm volatile(
        "mma.sync.aligned.m16n8k16.row.col.f32.f16.f16.f32 "
        "{%0,%1,%2,%3}, {%4,%5,%6,%7}, {%8,%9}, {%0,%1,%2,%3};"
        : "+f"(c[0]), "+f"(c[1]), "+f"(c[2]), "+f"(c[3])
        : "r"(a[0]), "r"(a[1]), "r"(a[2]), "r"(a[3]), "r"(b0), "r"(b1));
}

__device__ __forceinline__ void red_v2(float* gptr, float v0, float v1) {
    asm volatile("red.global.add.v2.f32 [%0], {%1, %2};"
                 :: "l"(gptr), "f"(v0), "f"(v1) : "memory");
}

__device__ __forceinline__ float softplus_fast(float r) {
    return (r > 15.f) ? r : __logf(1.f + __expf(r));
}

// ---------------------------------------------------------------------------
// Prep: out <- bias broadcast, KL slot <- 0, x -> fp16 scratch.
// ---------------------------------------------------------------------------
__global__ void vl_prep(const float* __restrict__ x,
                        const float* __restrict__ bmu,
                        const float* __restrict__ brho,
                        const float* __restrict__ epsb,
                        float* __restrict__ out, int out_size) {
    int i = blockIdx.x * blockDim.x + threadIdx.x;
    if (i < BATCH * OUT_F) {
        int col = i & (OUT_F - 1);
        out[i] = fmaf(softplus_fast(brho[col]), epsb[col], bmu[col]);
    } else if (i < out_size) {
        out[i] = 0.f;
    }
    if (i < BATCH * IN_F)
        g_x_h[i] = __float2half_rn(x[i]);
}

// ---------------------------------------------------------------------------
// Main fused kernel: 512 threads, warp owns one m16 tile
// ---------------------------------------------------------------------------
__global__ void __launch_bounds__(THREADS, 2)
vl_main(const float* __restrict__ mu, const float* __restrict__ rho,
        const float* __restrict__ epsw,
        float* __restrict__ out, float* __restrict__ klout) {
    extern __shared__ char smbase[];
    __half* Xs  = (__half*)smbase;                               // [2][256][XSH]
    float*  Raw = (float*)(smbase + XSTG * XS_BYTES);            // [4][3][1024]
    __shared__ float klred[16];

    const unsigned sbase = (unsigned)__cvta_generic_to_shared(smbase);
    const unsigned xs_b  = sbase;
    const unsigned wg_b  = sbase + XSTG * XS_BYTES + RSTG * RAW_BYTES;

    const int tid  = threadIdx.x;
    const int warp = tid >> 5;                 // 0..15
    const int lane = tid & 31;
    const int g    = lane >> 2;
    const int t    = lane & 3;

    const int ntile = blockIdx.x >> 2;
    const int kseg  = blockIdx.x & 3;
    const int n0    = ntile * NT;
    const int kbase = kseg * KSEG;
    const int m16   = warp * 16;

    float acc[8][4];
#pragma unroll
    for (int nt = 0; nt < 8; nt++)
#pragma unroll
        for (int i = 0; i < 4; i++) acc[nt][i] = 0.f;

    float klsum = 0.f;

    // Wgen: thread owns 2 consecutive elements of the 64x16 tile
    const int we   = tid * 2;                  // 0..1022
    const int wrow = we >> 4;                  // 0..63
    const int wk   = we & 15;

    // raw staging (NO duplicate): op1 for all threads covers streams 0,1;
    // op2 for tid<256 covers stream 2. 768 float4 total.
    const int  rs0  = tid >> 8;                // 0..1
    const int  ri0  = tid & 255;
    const long rg0  = (long)(n0 + (ri0 >> 2)) * IN_F + kbase + (ri0 & 3) * 4;
    const int  ri1  = tid;                     // valid when tid<256
    const long rg1  = (long)(n0 + (ri1 >> 2)) * IN_F + kbase + (ri1 & 3) * 4;
    const float* streams[3] = { mu, rho, epsw };

    // A ldmatrix offset (bytes): row = m16 + (lane&15), kofs = (lane>>4)*8
    const unsigned a_off =
        ((m16 + (lane & 15)) * XSH + ((lane >> 4) << 3)) * 2;
    // B ldmatrix base offset (pair p=0)
    const unsigned b_off0 =
        ((((lane >> 4) << 3) + (lane & 7)) * WSH + (((lane >> 3) & 1) << 3)) * 2;

    auto xPf = [&](int c) {                    // X chunk c -> stage c&1
        if (c < NCHUNK) {
            const int k0 = kbase + c * KC;
            __half* xd = Xs + (c & 1) * (BATCH * XSH);
            int row = tid >> 1;
            int seg = tid & 1;
            cp_async16(xd + row * XSH + seg * 8,
                       g_x_h + (long)row * IN_F + k0 + seg * 8);
        }
        asm volatile("cp.async.commit_group;");
    };
    auto rPf = [&](int c) {                    // weights chunk c -> stage c&3
        if (c < NCHUNK) {
            float* rd = Raw + (c & 3) * RAW_FL;
            const int k0 = c * KC;
            cp_async16(rd + rs0 * (NT * KC) + ri0 * 4,
                       streams[rs0] + rg0 + k0);
            if (tid < 256)
                cp_async16(rd + 2 * (NT * KC) + ri1 * 4,
                           streams[2] + rg1 + k0);
        }
        asm volatile("cp.async.commit_group;");
    };

    // Wgen(k): raw stage k&3 -> Wg[k&1]; KL with prior constants folded
    auto wgen = [&](int k) {
        const float* rb = Raw + (k & 3) * RAW_FL;
        float2 m2 = *reinterpret_cast<const float2*>(rb + 0 * NT * KC + we);
        float2 r2 = *reinterpret_cast<const float2*>(rb + 1 * NT * KC + we);
        float2 e2 = *reinterpret_cast<const float2*>(rb + 2 * NT * KC + we);
        const float mv[2] = {m2.x, m2.y};
        const float rv[2] = {r2.x, r2.y};
        const float ev[2] = {e2.x, e2.y};
        float wv[2];
#pragma unroll
        for (int q = 0; q < 2; q++) {
            float sg = __logf(1.f + __expf(rv[q]));    // softplus
            wv[q] = fmaf(sg, ev[q], mv[q]);
            klsum += fmaf(50.f, fmaf(sg, sg, mv[q] * mv[q]),
                          KL_C0 - __logf(sg));
        }
        __half2 p0 = __floats2half2_rn(wv[0], wv[1]);
        *reinterpret_cast<__half2*>(
            (__half*)(smbase + XSTG * XS_BYTES + RSTG * RAW_BYTES)
            + (k & 1) * (NT * WSH) + wrow * WSH + wk) = p0;
    };

    // ---- prologue: groups [raw0][raw1][X0][raw2]; land raw0; Wgen(0) ----
    rPf(0);
    rPf(1);
    xPf(0);
    rPf(2);
    asm volatile("cp.async.wait_group 3;");
    __syncthreads();
    wgen(0);

    for (int c = 0; c < NCHUNK; c++) {
        asm volatile("cp.async.wait_group 1;");  // X(c), raw(c+1) landed
        __syncthreads();                         // one barrier per chunk

        xPf(c + 1);                              // stage (c+1)&1
        rPf(c + 3);                              // stage (c+3)&3

        // ---- MMA(c) FIRST: tensor burst starts immediately ----
        const unsigned xa = xs_b + (c & 1) * XS_BYTES + a_off;
        unsigned a0[4];
        ldsm_x4(a0[0], a0[1], a0[2], a0[3], xa);

        const unsigned wb = wg_b + (c & 1) * WG_BYTES + b_off0;
#pragma unroll
        for (int p = 0; p < 4; p++) {
            unsigned b0, b1, b2, b3;
            ldsm_x4(b0, b1, b2, b3, wb + p * 16 * WSH * 2);
            mma_f16(acc[2 * p],     a0, b0, b1);
            mma_f16(acc[2 * p + 1], a0, b2, b3);
        }

        // ---- wgen(c+1) AFTER: MUFU overlaps the tensor pipe drain ----
        if (c + 1 < NCHUNK) wgen(c + 1);
    }

    // ---- epilogue: vector reductions (bias already in out) ----
    {
        int r0 = m16 + g;
#pragma unroll
        for (int nt = 0; nt < 8; nt++) {
            int col = n0 + nt * 8 + 2 * t;
            red_v2(&out[(long)r0 * OUT_F + col],       acc[nt][0], acc[nt][1]);
            red_v2(&out[(long)(r0 + 8) * OUT_F + col], acc[nt][2], acc[nt][3]);
        }
    }

    // ---- KL reduction ----
#pragma unroll
    for (int o = 16; o; o >>= 1)
        klsum += __shfl_xor_sync(0xFFFFFFFFu, klsum, o);
    if (lane == 0) klred[warp] = klsum;
    __syncthreads();
    if (tid == 0) {
        float s = 0.f;
#pragma unroll
        for (int i = 0; i < 16; i++) s += klred[i];
        atomicAdd(klout, s);
    }
}

// ---------------------------------------------------------------------------
extern "C" void kernel_launch(void* const* d_in, const int* in_sizes, int n_in,
                              void* d_out, int out_size) {
    const float* x    = (const float*)d_in[0];
    const float* wmu  = (const float*)d_in[1];
    const float* wrho = (const float*)d_in[2];
    const float* bmu  = (const float*)d_in[3];
    const float* brho = (const float*)d_in[4];
    const float* epsw = (const float*)d_in[5];
    const float* epsb = (const float*)d_in[6];
    float* out = (float*)d_out;

    int n = BATCH * IN_F;
    if (out_size > n) n = out_size;
    vl_prep<<<(n + 255) / 256, 256>>>(x, bmu, brho, epsb, out, out_size);

    cudaFuncSetAttribute(vl_main, cudaFuncAttributeMaxDynamicSharedMemorySize,
                         SMEM_BYTES);
    vl_main<<<(OUT_F / NT) * KSPLIT, THREADS, SMEM_BYTES>>>(
        wmu, wrho, epsw, out, out + (out_size - 1));
}